// round 12
// baseline (speedup 1.0000x reference)
#include <cuda_runtime.h>
#include <cuda_fp16.h>
#include <math.h>

#define NNODES 50000
#define NEDGES 1000000
#define NDIM   16
#define EMB    64
#define DOUT   64
#define NHEADS 8
#define EADIM  8
#define SLOPE  0.01f
#define LN_EPS 1e-5f
#define SCANB  49    // ceil(50000/1024)
#define NPB    80    // nodes per block in GEMM kernels (50000 = 625*80)

// ---------------- scratch ----------------
__device__ __align__(128) float  g_x[(size_t)NNODES*EMB];
__device__ __align__(128) __half g_eap16[(size_t)NEDGES*8];  // head projections, fp16, CSR order
__device__ __align__(128) float  g_eap2[NEDGES];
__device__ __align__(128) unsigned char g_h8[(size_t)NNODES*512]; // h [n][head][64] e4m3
__device__ __align__(128) __half g_hph[(size_t)NHEADS*NNODES*DOUT]; // stores elu(elu(hp))
__device__ __align__(128) __half g_h2h[(size_t)NNODES*DOUT];
__device__ __align__(128) float  g_asrc8[NNODES*8];
__device__ __align__(128) float  g_atgt8[NNODES*8];
__device__ __align__(128) float  g_asrc2[NNODES];
__device__ __align__(128) float  g_atgt2[NNODES];
__device__ __align__(128) int g_src[NEDGES];
__device__ __align__(128) int g_tgt[NEDGES];
__device__ __align__(128) int g_tgtc[NEDGES];
__device__ __align__(128) int g_row[NNODES+1];
__device__ __align__(128) int g_cur[NNODES];
__device__ __align__(128) int g_cnt[NNODES];
__device__ __align__(128) int g_part[64];
__device__ int g_flag;

__device__ __forceinline__ float eluf(float x){ return x > 0.f ? x : expm1f(x); }
__device__ __forceinline__ float lrelu(float x){ return x >= 0.f ? x : SLOPE * x; }

typedef unsigned long long u64t;
__device__ __forceinline__ u64t pack2(float lo, float hi){
  u64t r; asm("mov.b64 %0, {%1,%2};" : "=l"(r) : "f"(lo), "f"(hi)); return r;
}
__device__ __forceinline__ u64t ffma2(u64t a, u64t b, u64t c){
  u64t d; asm("fma.rn.f32x2 %0, %1, %2, %3;" : "=l"(d) : "l"(a), "l"(b), "l"(c)); return d;
}
__device__ __forceinline__ float2 unpack2(u64t v){
  float2 f; asm("mov.b64 {%0,%1}, %2;" : "=f"(f.x), "=f"(f.y) : "l"(v)); return f;
}
// fp8 e4m3 pair -> float2 (HW converter)
__device__ __forceinline__ float2 fp8x2_f2(unsigned v16){
  unsigned r; asm("cvt.rn.f16x2.e4m3x2 %0, %1;" : "=r"(r) : "h"((unsigned short)v16));
  return __half22float2(*(__half2*)&r);
}
// two floats -> e4m3 pair (lo = a, hi = b)
__device__ __forceinline__ unsigned short f2_fp8x2(float lo, float hi){
  unsigned short d;
  asm("cvt.rn.satfinite.e4m3x2.f32 %0, %1, %2;" : "=h"(d) : "f"(hi), "f"(lo));
  return d;
}

// ---------------- streams for phase overlap ----------------
struct StreamsHolder {
  cudaStream_t s2;
  cudaEvent_t e0, e1;
  StreamsHolder(){
    cudaStreamCreateWithFlags(&s2, cudaStreamNonBlocking);
    cudaEventCreateWithFlags(&e0, cudaEventDisableTiming);
    cudaEventCreateWithFlags(&e1, cudaEventDisableTiming);
  }
};
static StreamsHolder g_sh;

// ---------------- init: dtype detect + zero counters + scan sentinels ----------------
__global__ void k_init(const void* ei){
  int i = blockIdx.x*blockDim.x + threadIdx.x;
  if(i < NNODES) g_cnt[i] = 0;
  if(i < 64) g_part[i] = -1;
  if(i == 0){
    const long long* p = (const long long*)ei;
    int is64 = 1;
    for(int k = 0; k < 64; k++){
      long long v = p[k];
      if(v < 0 || v >= 4294967296LL) is64 = 0;
    }
    g_flag = is64;
  }
}

__global__ void k_convert(const void* ei){
  int e = blockIdx.x*blockDim.x + threadIdx.x;
  if(e >= NEDGES) return;
  int s, t;
  if(g_flag){
    const long long* p = (const long long*)ei;
    s = (int)p[e]; t = (int)p[NEDGES + e];
  } else {
    const int* p = (const int*)ei;
    s = p[e]; t = p[NEDGES + e];
  }
  g_src[e] = s; g_tgt[e] = t;
  atomicAdd(&g_cnt[s], 1);
}

// ---------------- single-pass scan (StreamScan: chained block lookback) ----------------
__global__ void k_scanF(){
  __shared__ int swarp[32];
  __shared__ int sprev;
  int b = blockIdx.x;
  int i = b*1024 + threadIdx.x;
  int lane = threadIdx.x & 31, wid = threadIdx.x >> 5;
  int v = (i < NNODES) ? g_cnt[i] : 0;
  int x = v;
  #pragma unroll
  for(int o = 1; o < 32; o <<= 1){
    int y = __shfl_up_sync(0xffffffffu, x, o);
    if(lane >= o) x += y;
  }
  if(lane == 31) swarp[wid] = x;
  __syncthreads();
  if(wid == 0){
    int s = swarp[lane];
    #pragma unroll
    for(int o = 1; o < 32; o <<= 1){
      int y = __shfl_up_sync(0xffffffffu, s, o);
      if(lane >= o) s += y;
    }
    swarp[lane] = s;
  }
  __syncthreads();
  int base = wid ? swarp[wid-1] : 0;
  int incl = base + x;
  if(threadIdx.x == 0){
    int prev = 0;
    if(b > 0){
      while((prev = atomicAdd(&g_part[b-1], 0)) < 0){}
    }
    atomicExch(&g_part[b], prev + swarp[31]);
    sprev = prev;
  }
  __syncthreads();
  int prev = sprev;
  if(i < NNODES){
    int r = prev + incl - v;
    g_row[i] = r; g_cur[i] = r;
  }
  if(i == 0) g_row[NNODES] = NEDGES;
}

// ---------------- node MLP ----------------
__global__ void k_node_mlp(const float* __restrict__ X, const float* __restrict__ w,
                           const float* __restrict__ b, const float* __restrict__ g,
                           const float* __restrict__ beta){
  __shared__ float sw[NDIM*EMB];
  __shared__ float sb[EMB], sg[EMB], sbt[EMB];
  for(int i = threadIdx.x; i < NDIM*EMB; i += blockDim.x) sw[i] = w[i];
  for(int i = threadIdx.x; i < EMB; i += blockDim.x){ sb[i]=b[i]; sg[i]=g[i]; sbt[i]=beta[i]; }
  __syncthreads();
  int n = blockIdx.x*blockDim.x + threadIdx.x;
  if(n >= NNODES) return;
  float xin[NDIM];
  const float4* px = (const float4*)(X + (size_t)n*NDIM);
  #pragma unroll
  for(int q = 0; q < 4; q++){
    float4 v = px[q];
    xin[q*4+0]=v.x; xin[q*4+1]=v.y; xin[q*4+2]=v.z; xin[q*4+3]=v.w;
  }
  u64t xk2[NDIM];
  #pragma unroll
  for(int k = 0; k < NDIM; k++) xk2[k] = pack2(xin[k], xin[k]);
  float y[EMB]; float sum = 0.f;
  #pragma unroll
  for(int jp = 0; jp < EMB/2; jp++){
    u64t acc = pack2(sb[2*jp], sb[2*jp+1]);
    #pragma unroll
    for(int k = 0; k < NDIM; k++)
      acc = ffma2(xk2[k], *(const u64t*)&sw[k*EMB + 2*jp], acc);
    float2 f = unpack2(acc);
    y[2*jp] = f.x; y[2*jp+1] = f.y;
    sum += f.x + f.y;
  }
  float mu = sum * (1.f/EMB);
  float vs = 0.f;
  #pragma unroll
  for(int j = 0; j < EMB; j++){ float d = y[j]-mu; vs += d*d; }
  float inv = rsqrtf(vs*(1.f/EMB) + LN_EPS);
  #pragma unroll
  for(int j = 0; j < EMB; j++){
    float v = (y[j]-mu)*inv*sg[j] + sbt[j];
    g_x[(size_t)n*EMB + j] = fmaxf(v, 0.f);
  }
}

// ---------------- edge MLP + 9 projections + fused CSR scatter (1 thread/edge) ----
__global__ void k_edge_mlp(const float* __restrict__ EA, const float* __restrict__ w,
                           const float* __restrict__ b, const float* __restrict__ g,
                           const float* __restrict__ beta, const float* __restrict__ gat_a,
                           const float* __restrict__ out_a){
  __shared__ float sw[EADIM*EMB];
  __shared__ float sb[EMB], sg[EMB], sbt[EMB];
  __shared__ float sa[9][EMB];
  for(int i = threadIdx.x; i < EADIM*EMB; i += blockDim.x) sw[i] = w[i];
  for(int i = threadIdx.x; i < EMB; i += blockDim.x){ sb[i]=b[i]; sg[i]=g[i]; sbt[i]=beta[i]; }
  for(int i = threadIdx.x; i < 9*EMB; i += blockDim.x){
    int p = i/EMB, j = i%EMB;
    sa[p][j] = (p < 8) ? gat_a[p*192 + 128 + j] : out_a[128 + j];
  }
  __syncthreads();
  int e = blockIdx.x*blockDim.x + threadIdx.x;
  if(e >= NEDGES) return;
  const float4* pe = (const float4*)(EA + (size_t)e*EADIM);
  float4 a0 = pe[0], a1 = pe[1];
  float xin[EADIM] = {a0.x,a0.y,a0.z,a0.w,a1.x,a1.y,a1.z,a1.w};
  u64t xk2[EADIM];
  #pragma unroll
  for(int k = 0; k < EADIM; k++) xk2[k] = pack2(xin[k], xin[k]);
  float y[EMB]; float sum = 0.f;
  #pragma unroll
  for(int jp = 0; jp < EMB/2; jp++){
    u64t acc = pack2(sb[2*jp], sb[2*jp+1]);
    #pragma unroll
    for(int k = 0; k < EADIM; k++)
      acc = ffma2(xk2[k], *(const u64t*)&sw[k*EMB + 2*jp], acc);
    float2 f = unpack2(acc);
    y[2*jp] = f.x; y[2*jp+1] = f.y;
    sum += f.x + f.y;
  }
  float mu = sum*(1.f/EMB);
  float vs = 0.f;
  #pragma unroll
  for(int j = 0; j < EMB; j++){ float d = y[j]-mu; vs += d*d; }
  float inv = rsqrtf(vs*(1.f/EMB) + LN_EPS);
  u64t y2[EMB/2];
  #pragma unroll
  for(int j = 0; j < EMB; j += 2){
    float v0 = fmaxf((y[j]-mu)*inv*sg[j] + sbt[j], 0.f);
    float v1 = fmaxf((y[j+1]-mu)*inv*sg[j+1] + sbt[j+1], 0.f);
    y2[j/2] = pack2(v0, v1);
  }
  float pr[9];
  #pragma unroll
  for(int p = 0; p < 9; p++){
    u64t acc = 0;
    #pragma unroll
    for(int jp = 0; jp < EMB/2; jp++)
      acc = ffma2(y2[jp], *(const u64t*)&sa[p][2*jp], acc);
    float2 f = unpack2(acc);
    pr[p] = f.x + f.y;
  }
  int s = g_src[e];
  int pos = atomicAdd(&g_cur[s], 1);
  g_tgtc[pos] = g_tgt[e];
  __half2 q0 = __floats2half2_rn(pr[0], pr[1]);
  __half2 q1 = __floats2half2_rn(pr[2], pr[3]);
  __half2 q2 = __floats2half2_rn(pr[4], pr[5]);
  __half2 q3 = __floats2half2_rn(pr[6], pr[7]);
  uint4 st;
  st.x = *(unsigned*)&q0; st.y = *(unsigned*)&q1;
  st.z = *(unsigned*)&q2; st.w = *(unsigned*)&q3;
  *(uint4*)&g_eap16[(size_t)pos*8] = st;
  g_eap2[pos] = pr[8];
}

// -------- all-heads h = x @ W -> e4m3 interleaved [n][head][64] -----
__global__ void k_head_h(const float* __restrict__ gat_W, const float* __restrict__ gat_a){
  __shared__ float sx[NPB*EMB];   // 20KB
  __shared__ float sw[EMB*DOUT];  // 16KB
  int n0 = blockIdx.x*NPB;
  int t = threadIdx.x;
  const float4* px = (const float4*)(g_x + (size_t)n0*EMB);
  #pragma unroll
  for(int i = 0; i < 5; i++)
    ((float4*)sx)[t + 256*i] = px[t + 256*i];
  int nn = t >> 4;
  int j0 = (t & 15)*4;
  for(int head = 0; head < NHEADS; head++){
    __syncthreads();
    const float* W = gat_W + (size_t)head*EMB*DOUT;
    #pragma unroll
    for(int i = 0; i < 4; i++)
      ((float4*)sw)[t + 256*i] = ((const float4*)W)[t + 256*i];
    __syncthreads();
    const float* a = gat_a + head*192;
    float aj0 = a[j0],    aj1 = a[j0+1],    aj2 = a[j0+2],    aj3 = a[j0+3];
    float bj0 = a[64+j0], bj1 = a[64+j0+1], bj2 = a[64+j0+2], bj3 = a[64+j0+3];
    #pragma unroll
    for(int g = 0; g < 5; g++){
      u64t acc01 = 0, acc23 = 0;
      const float* xr = &sx[(g*16 + nn)*EMB];
      #pragma unroll
      for(int k = 0; k < EMB; k++){
        float xv = xr[k];
        u64t xv2 = pack2(xv, xv);
        acc01 = ffma2(xv2, *(const u64t*)&sw[k*DOUT + j0],     acc01);
        acc23 = ffma2(xv2, *(const u64t*)&sw[k*DOUT + j0 + 2], acc23);
      }
      float2 f01 = unpack2(acc01), f23 = unpack2(acc23);
      float4 acc = {f01.x, f01.y, f23.x, f23.y};
      int n = n0 + g*16 + nn;
      unsigned short p01 = f2_fp8x2(acc.x, acc.y);
      unsigned short p23 = f2_fp8x2(acc.z, acc.w);
      unsigned pk = ((unsigned)p23 << 16) | (unsigned)p01;
      *(unsigned*)&g_h8[(size_t)n*512 + head*64 + j0] = pk;
      float ps = acc.x*aj0 + acc.y*aj1 + acc.z*aj2 + acc.w*aj3;
      float pt = acc.x*bj0 + acc.y*bj1 + acc.z*bj2 + acc.w*bj3;
      #pragma unroll
      for(int o = 8; o >= 1; o >>= 1){
        ps += __shfl_xor_sync(0xffffffffu, ps, o);
        pt += __shfl_xor_sync(0xffffffffu, pt, o);
      }
      if((t & 15) == 0){
        g_asrc8[n*8 + head] = ps;
        g_atgt8[n*8 + head] = pt;
      }
    }
  }
}

// ------- FUSED layer-1: 2 warps per node (4 heads each), fp8 gathers, unroll 4 -------
__global__ void k_fagg1(){
  int gw = (blockIdx.x*blockDim.x + threadIdx.x) >> 5;
  int lane = threadIdx.x & 31;
  if(gw >= 2*NNODES) return;
  int n = gw >> 1;
  int grp = gw & 1;
  int hb = grp*4;
  int r0 = g_row[n], r1 = g_row[n+1];
  float asl = (lane < 4) ? g_asrc8[n*8 + hb + lane] : 0.f;
  int hsub = lane >> 3;
  float acc[8];
  #pragma unroll
  for(int i = 0; i < 8; i++) acc[i] = 0.f;
  float den = 0.f;
  int pos = r0;
  for(; pos + 3 < r1; pos += 4){
    // batch index loads
    int tg0 = g_tgtc[pos];
    int tg1 = g_tgtc[pos+1];
    int tg2 = g_tgtc[pos+2];
    int tg3 = g_tgtc[pos+3];
    // issue all 4 h gathers immediately
    uint2 v0 = *(const uint2*)(g_h8 + (size_t)tg0*512 + grp*256 + lane*8);
    uint2 v1 = *(const uint2*)(g_h8 + (size_t)tg1*512 + grp*256 + lane*8);
    uint2 v2 = *(const uint2*)(g_h8 + (size_t)tg2*512 + grp*256 + lane*8);
    uint2 v3 = *(const uint2*)(g_h8 + (size_t)tg3*512 + grp*256 + lane*8);
    // score operands (lanes 0-3 only)
    float e0=0.f,e1=0.f,e2=0.f,e3=0.f,t0=0.f,t1=0.f,t2=0.f,t3=0.f;
    if(lane < 4){
      e0 = __half2float(g_eap16[(size_t)pos*8 + hb + lane]);
      e1 = __half2float(g_eap16[(size_t)(pos+1)*8 + hb + lane]);
      e2 = __half2float(g_eap16[(size_t)(pos+2)*8 + hb + lane]);
      e3 = __half2float(g_eap16[(size_t)(pos+3)*8 + hb + lane]);
      t0 = g_atgt8[tg0*8 + hb + lane];
      t1 = g_atgt8[tg1*8 + hb + lane];
      t2 = g_atgt8[tg2*8 + hb + lane];
      t3 = g_atgt8[tg3*8 + hb + lane];
    }
    float ev0 = __expf(lrelu(asl + t0 + e0));
    float ev1 = __expf(lrelu(asl + t1 + e1));
    float ev2 = __expf(lrelu(asl + t2 + e2));
    float ev3 = __expf(lrelu(asl + t3 + e3));
    if(lane < 4) den += (ev0 + ev1) + (ev2 + ev3);
    float w0 = __shfl_sync(0xffffffffu, ev0, hsub);
    float w1 = __shfl_sync(0xffffffffu, ev1, hsub);
    float w2 = __shfl_sync(0xffffffffu, ev2, hsub);
    float w3 = __shfl_sync(0xffffffffu, ev3, hsub);
    #pragma unroll
    for(int q = 0; q < 2; q++){
      unsigned u0 = q ? v0.y : v0.x;
      unsigned u1 = q ? v1.y : v1.x;
      unsigned u2 = q ? v2.y : v2.x;
      unsigned u3 = q ? v3.y : v3.x;
      float2 a0 = fp8x2_f2(u0 & 0xffffu), b0 = fp8x2_f2(u0 >> 16);
      float2 a1 = fp8x2_f2(u1 & 0xffffu), b1 = fp8x2_f2(u1 >> 16);
      float2 a2 = fp8x2_f2(u2 & 0xffffu), b2 = fp8x2_f2(u2 >> 16);
      float2 a3 = fp8x2_f2(u3 & 0xffffu), b3 = fp8x2_f2(u3 >> 16);
      acc[4*q]   += (w0*a0.x + w1*a1.x) + (w2*a2.x + w3*a3.x);
      acc[4*q+1] += (w0*a0.y + w1*a1.y) + (w2*a2.y + w3*a3.y);
      acc[4*q+2] += (w0*b0.x + w1*b1.x) + (w2*b2.x + w3*b3.x);
      acc[4*q+3] += (w0*b0.y + w1*b1.y) + (w2*b2.y + w3*b3.y);
    }
  }
  for(; pos < r1; pos++){
    int tg = g_tgtc[pos];
    uint2 va = *(const uint2*)(g_h8 + (size_t)tg*512 + grp*256 + lane*8);
    float e0 = 0.f, t0 = 0.f;
    if(lane < 4){
      e0 = __half2float(g_eap16[(size_t)pos*8 + hb + lane]);
      t0 = g_atgt8[tg*8 + hb + lane];
    }
    float ev = __expf(lrelu(asl + t0 + e0));
    if(lane < 4) den += ev;
    float w0 = __shfl_sync(0xffffffffu, ev, hsub);
    #pragma unroll
    for(int q = 0; q < 2; q++){
      unsigned ua = q ? va.y : va.x;
      float2 fa0 = fp8x2_f2(ua & 0xffffu);
      float2 fa1 = fp8x2_f2(ua >> 16);
      acc[4*q]   += w0*fa0.x;
      acc[4*q+1] += w0*fa0.y;
      acc[4*q+2] += w0*fa1.x;
      acc[4*q+3] += w0*fa1.y;
    }
  }
  float rd = 1.f/(den + 1e-16f);
  float rdm = __shfl_sync(0xffffffffu, rd, hsub);
  int hglob = hb + hsub;
  int jj = (lane & 7)*8;
  uint4 o; __half2* po = (__half2*)&o;
  #pragma unroll
  for(int q = 0; q < 4; q++){
    float v0 = eluf(eluf(acc[2*q]*rdm));
    float v1 = eluf(eluf(acc[2*q+1]*rdm));
    po[q] = __floats2half2_rn(v0, v1);
  }
  *(uint4*)&g_hph[((size_t)hglob*NNODES + n)*64 + jj] = o;
}

// ---------------- final layer h2 = hph_concat @ out_W (elu pre-applied) ------------
__global__ void k_out_h(const float* __restrict__ out_W, const float* __restrict__ out_a){
  __shared__ float sx[NPB*EMB];   // 20KB
  __shared__ float sw[EMB*DOUT];  // 16KB
  int n0 = blockIdx.x*NPB;
  int t = threadIdx.x;
  int nn = t >> 4;
  int j0 = (t & 15)*4;
  u64t a01[5], a23[5];
  #pragma unroll
  for(int g = 0; g < 5; g++){ a01[g] = 0; a23[g] = 0; }
  for(int c = 0; c < NHEADS; c++){
    __syncthreads();
    #pragma unroll
    for(int i = 0; i < 4; i++)
      ((float4*)sw)[t + 256*i] = ((const float4*)(out_W + (size_t)c*EMB*DOUT))[t + 256*i];
    const uint2* hp = (const uint2*)(g_hph + ((size_t)c*NNODES + n0)*64);
    #pragma unroll
    for(int i = 0; i < 5; i++){
      uint2 u = hp[t + 256*i];
      float2 fa = __half22float2(*(const __half2*)&u.x);
      float2 fb = __half22float2(*(const __half2*)&u.y);
      float4 xv4 = {fa.x, fa.y, fb.x, fb.y};
      ((float4*)sx)[t + 256*i] = xv4;
    }
    __syncthreads();
    #pragma unroll
    for(int k = 0; k < EMB; k++){
      u64t w01 = *(const u64t*)&sw[k*DOUT + j0];
      u64t w23 = *(const u64t*)&sw[k*DOUT + j0 + 2];
      #pragma unroll
      for(int g = 0; g < 5; g++){
        float xv = sx[(g*16 + nn)*EMB + k];
        u64t xv2 = pack2(xv, xv);
        a01[g] = ffma2(xv2, w01, a01[g]);
        a23[g] = ffma2(xv2, w23, a23[g]);
      }
    }
  }
  #pragma unroll
  for(int g = 0; g < 5; g++){
    float2 f01 = unpack2(a01[g]), f23 = unpack2(a23[g]);
    float4 acc = {f01.x, f01.y, f23.x, f23.y};
    int n = n0 + g*16 + nn;
    __half2 lo = __floats2half2_rn(acc.x, acc.y);
    __half2 hi = __floats2half2_rn(acc.z, acc.w);
    uint2 u; u.x = *(unsigned*)&lo; u.y = *(unsigned*)&hi;
    *(uint2*)&g_h2h[(size_t)n*64 + j0] = u;
    float ps = acc.x*out_a[j0] + acc.y*out_a[j0+1] + acc.z*out_a[j0+2] + acc.w*out_a[j0+3];
    float pt = acc.x*out_a[64+j0] + acc.y*out_a[64+j0+1] + acc.z*out_a[64+j0+2] + acc.w*out_a[64+j0+3];
    #pragma unroll
    for(int o = 8; o >= 1; o >>= 1){
      ps += __shfl_xor_sync(0xffffffffu, ps, o);
      pt += __shfl_xor_sync(0xffffffffu, pt, o);
    }
    if((t & 15) == 0){
      g_asrc2[n] = ps;
      g_atgt2[n] = pt;
    }
  }
}

// -------- fused layer-2 aggregation + elu + log_softmax (writes d_out directly) ----
__global__ void k_fagg2ls(float* __restrict__ out){
  int warp = (blockIdx.x*blockDim.x + threadIdx.x) >> 5;
  int lane = threadIdx.x & 31;
  if(warp >= NNODES) return;
  int n = warp;
  int r0 = g_row[n], r1 = g_row[n+1];
  float as2 = g_asrc2[n];
  float ax = 0.f, ay = 0.f, den = 0.f;
  int pos = r0;
  for(; pos + 1 < r1; pos += 2){
    int tg0 = g_tgtc[pos];
    int tg1 = g_tgtc[pos+1];
    float2 v0 = __half22float2(((const __half2*)(g_h2h + (size_t)tg0*DOUT))[lane]);
    float2 v1 = __half22float2(((const __half2*)(g_h2h + (size_t)tg1*DOUT))[lane]);
    float at0 = g_atgt2[tg0];
    float at1 = g_atgt2[tg1];
    float ep0 = g_eap2[pos];
    float ep1 = g_eap2[pos+1];
    float ev0 = __expf(lrelu(as2 + at0 + ep0));
    float ev1 = __expf(lrelu(as2 + at1 + ep1));
    den += ev0 + ev1;
    ax += ev0*v0.x + ev1*v1.x;
    ay += ev0*v0.y + ev1*v1.y;
  }
  if(pos < r1){
    int tg = g_tgtc[pos];
    float2 v = __half22float2(((const __half2*)(g_h2h + (size_t)tg*DOUT))[lane]);
    float ev = __expf(lrelu(as2 + g_atgt2[tg] + g_eap2[pos]));
    den += ev;
    ax += ev*v.x; ay += ev*v.y;
  }
  float rd = 1.f/(den + 1e-16f);
  float v0 = eluf(ax*rd);
  float v1 = eluf(ay*rd);
  float m = fmaxf(v0, v1);
  #pragma unroll
  for(int o = 16; o >= 1; o >>= 1) m = fmaxf(m, __shfl_xor_sync(0xffffffffu, m, o));
  float s = __expf(v0 - m) + __expf(v1 - m);
  #pragma unroll
  for(int o = 16; o >= 1; o >>= 1) s += __shfl_xor_sync(0xffffffffu, s, o);
  float l = logf(s);
  float2 o2 = {v0 - m - l, v1 - m - l};
  ((float2*)(out + (size_t)n*DOUT))[lane] = o2;
}

// ---------------- launcher ----------------
extern "C" void kernel_launch(void* const* d_in, const int* in_sizes, int n_in,
                              void* d_out, int out_size){
  const float *X=0, *EA=0, *w_node=0, *w_edge=0, *gatW=0, *gata=0, *outW=0, *outa=0;
  const void* ei = 0;
  const float* v64[8]; int n64 = 0; int nbig = 0;
  for(int i = 0; i < n_in; i++){
    switch(in_sizes[i]){
      case 800000:  X    = (const float*)d_in[i]; break;
      case 8000000: EA   = (const float*)d_in[i]; break;
      case 2000000: ei   = d_in[i]; break;
      case 1024:    w_node = (const float*)d_in[i]; break;
      case 512:     w_edge = (const float*)d_in[i]; break;
      case 1536:    gata = (const float*)d_in[i]; break;
      case 192:     outa = (const float*)d_in[i]; break;
      case 32768:   if(nbig++ == 0) gatW = (const float*)d_in[i];
                    else            outW = (const float*)d_in[i];
                    break;
      case 64:      if(n64 < 8) v64[n64++] = (const float*)d_in[i]; break;
      default: break;
    }
  }
  const float* b_node = v64[0]; const float* g_node = v64[1]; const float* beta_node = v64[2];
  const float* b_edge = v64[3]; const float* g_edge = v64[4]; const float* beta_edge = v64[5];

  // fork node-side chain (node_mlp -> head_h) onto stream s2
  cudaEventRecord(g_sh.e0, 0);
  cudaStreamWaitEvent(g_sh.s2, g_sh.e0, 0);
  k_node_mlp<<<(NNODES + 255)/256, 256, 0, g_sh.s2>>>(X, w_node, b_node, g_node, beta_node);
  k_head_h<<<NNODES/NPB, 256, 0, g_sh.s2>>>(gatW, gata);
  cudaEventRecord(g_sh.e1, g_sh.s2);

  // edge-side chain on default stream: CSR build + edge MLP
  k_init<<<(NNODES + 255)/256, 256>>>(ei);
  k_convert<<<(NEDGES + 255)/256, 256>>>(ei);
  k_scanF<<<SCANB, 1024>>>();
  k_edge_mlp<<<(NEDGES + 127)/128, 128>>>(EA, w_edge, b_edge, g_edge, beta_edge, gata, outa);

  // join: fagg1 needs both chains
  cudaStreamWaitEvent(0, g_sh.e1, 0);

  // layer 1: fused softmax-aggregation, 2 warps per node, fp8 gathers
  k_fagg1<<<(2*NNODES*32 + 255)/256, 256>>>();

  // layer 2
  k_out_h<<<NNODES/NPB, 256>>>(outW, outa);
  k_fagg2ls<<<(NNODES*32 + 255)/256, 256>>>((float*)d_out);
}

// round 14
// speedup vs baseline: 1.0201x; 1.0201x over previous
#include <cuda_runtime.h>
#include <cuda_fp16.h>
#include <math.h>

#define NNODES 50000
#define NEDGES 1000000
#define NDIM   16
#define EMB    64
#define DOUT   64
#define NHEADS 8
#define EADIM  8
#define SLOPE  0.01f
#define LN_EPS 1e-5f
#define SCANB  49    // ceil(50000/1024)
#define NPB    80    // nodes per block in GEMM kernels (50000 = 625*80)

// ---------------- scratch ----------------
__device__ __align__(128) float  g_x[(size_t)NNODES*EMB];
__device__ __align__(128) __half g_eap16[(size_t)NEDGES*8];  // head projections, fp16, CSR order
__device__ __align__(128) float  g_eap2[NEDGES];
__device__ __align__(128) unsigned char g_h8[(size_t)NNODES*512]; // h [n][head][64] e4m3
__device__ __align__(128) __half g_hph[(size_t)NHEADS*NNODES*DOUT]; // stores elu(elu(hp))
__device__ __align__(128) __half g_h2h[(size_t)NNODES*DOUT];
__device__ __align__(128) float  g_asrc8[NNODES*8];
__device__ __align__(128) float  g_atgt8[NNODES*8];
__device__ __align__(128) float  g_asrc2[NNODES];
__device__ __align__(128) float  g_atgt2[NNODES];
__device__ __align__(128) int g_src[NEDGES];
__device__ __align__(128) int g_tgt[NEDGES];
__device__ __align__(128) int g_tgtc[NEDGES];
__device__ __align__(128) int g_row[NNODES+1];
__device__ __align__(128) int g_cur[NNODES];
__device__ __align__(128) int g_cnt[NNODES];
__device__ __align__(128) int g_part[64];
__device__ int g_flag;

__device__ __forceinline__ float eluf(float x){ return x > 0.f ? x : expm1f(x); }
__device__ __forceinline__ float lrelu(float x){ return x >= 0.f ? x : SLOPE * x; }

typedef unsigned long long u64t;
__device__ __forceinline__ u64t pack2(float lo, float hi){
  u64t r; asm("mov.b64 %0, {%1,%2};" : "=l"(r) : "f"(lo), "f"(hi)); return r;
}
__device__ __forceinline__ u64t ffma2(u64t a, u64t b, u64t c){
  u64t d; asm("fma.rn.f32x2 %0, %1, %2, %3;" : "=l"(d) : "l"(a), "l"(b), "l"(c)); return d;
}
__device__ __forceinline__ float2 unpack2(u64t v){
  float2 f; asm("mov.b64 {%0,%1}, %2;" : "=f"(f.x), "=f"(f.y) : "l"(v)); return f;
}
// fp8 e4m3 pair -> float2 (HW converter)
__device__ __forceinline__ float2 fp8x2_f2(unsigned v16){
  unsigned r; asm("cvt.rn.f16x2.e4m3x2 %0, %1;" : "=r"(r) : "h"((unsigned short)v16));
  return __half22float2(*(__half2*)&r);
}
// two floats -> e4m3 pair (lo = a, hi = b)
__device__ __forceinline__ unsigned short f2_fp8x2(float lo, float hi){
  unsigned short d;
  asm("cvt.rn.satfinite.e4m3x2.f32 %0, %1, %2;" : "=h"(d) : "f"(hi), "f"(lo));
  return d;
}

// ---------------- streams for phase overlap ----------------
struct StreamsHolder {
  cudaStream_t s2;
  cudaEvent_t e0, e1;
  StreamsHolder(){
    cudaStreamCreateWithFlags(&s2, cudaStreamNonBlocking);
    cudaEventCreateWithFlags(&e0, cudaEventDisableTiming);
    cudaEventCreateWithFlags(&e1, cudaEventDisableTiming);
  }
};
static StreamsHolder g_sh;

// ---------------- init: dtype detect + zero counters ----------------
__global__ void k_init(const void* ei){
  int i = blockIdx.x*blockDim.x + threadIdx.x;
  if(i < NNODES) g_cnt[i] = 0;
  if(i == 0){
    const long long* p = (const long long*)ei;
    int is64 = 1;
    for(int k = 0; k < 64; k++){
      long long v = p[k];
      if(v < 0 || v >= 4294967296LL) is64 = 0;
    }
    g_flag = is64;
  }
}

__global__ void k_convert(const void* ei){
  int e = blockIdx.x*blockDim.x + threadIdx.x;
  if(e >= NEDGES) return;
  int s, t;
  if(g_flag){
    const long long* p = (const long long*)ei;
    s = (int)p[e]; t = (int)p[NEDGES + e];
  } else {
    const int* p = (const int*)ei;
    s = p[e]; t = p[NEDGES + e];
  }
  g_src[e] = s; g_tgt[e] = t;
  atomicAdd(&g_cnt[s], 1);
}

// ---------------- parallel scan (3 phases) ----------------
__global__ void k_scan1(){
  __shared__ int swarp[32];
  int i = blockIdx.x*1024 + threadIdx.x;
  int lane = threadIdx.x & 31, wid = threadIdx.x >> 5;
  int v = (i < NNODES) ? g_cnt[i] : 0;
  int x = v;
  #pragma unroll
  for(int o = 1; o < 32; o <<= 1){
    int y = __shfl_up_sync(0xffffffffu, x, o);
    if(lane >= o) x += y;
  }
  if(lane == 31) swarp[wid] = x;
  __syncthreads();
  if(wid == 0){
    int s = swarp[lane];
    #pragma unroll
    for(int o = 1; o < 32; o <<= 1){
      int y = __shfl_up_sync(0xffffffffu, s, o);
      if(lane >= o) s += y;
    }
    swarp[lane] = s;
  }
  __syncthreads();
  int base = wid ? swarp[wid-1] : 0;
  int incl = base + x;
  if(i < NNODES) g_row[i] = incl - v;
  if(threadIdx.x == 1023) g_part[blockIdx.x] = incl;
}

__global__ void k_scan2(){
  if(threadIdx.x == 0){
    int s = 0;
    for(int i = 0; i < SCANB; i++){ int v = g_part[i]; g_part[i] = s; s += v; }
  }
}

__global__ void k_scan3(){
  int i = blockIdx.x*1024 + threadIdx.x;
  if(i < NNODES){
    int r = g_row[i] + g_part[blockIdx.x];
    g_row[i] = r; g_cur[i] = r;
  }
  if(i == 0) g_row[NNODES] = NEDGES;
}

// ---------------- node MLP ----------------
__global__ void k_node_mlp(const float* __restrict__ X, const float* __restrict__ w,
                           const float* __restrict__ b, const float* __restrict__ g,
                           const float* __restrict__ beta){
  __shared__ float sw[NDIM*EMB];
  __shared__ float sb[EMB], sg[EMB], sbt[EMB];
  for(int i = threadIdx.x; i < NDIM*EMB; i += blockDim.x) sw[i] = w[i];
  for(int i = threadIdx.x; i < EMB; i += blockDim.x){ sb[i]=b[i]; sg[i]=g[i]; sbt[i]=beta[i]; }
  __syncthreads();
  int n = blockIdx.x*blockDim.x + threadIdx.x;
  if(n >= NNODES) return;
  float xin[NDIM];
  const float4* px = (const float4*)(X + (size_t)n*NDIM);
  #pragma unroll
  for(int q = 0; q < 4; q++){
    float4 v = px[q];
    xin[q*4+0]=v.x; xin[q*4+1]=v.y; xin[q*4+2]=v.z; xin[q*4+3]=v.w;
  }
  u64t xk2[NDIM];
  #pragma unroll
  for(int k = 0; k < NDIM; k++) xk2[k] = pack2(xin[k], xin[k]);
  float y[EMB]; float sum = 0.f;
  #pragma unroll
  for(int jp = 0; jp < EMB/2; jp++){
    u64t acc = pack2(sb[2*jp], sb[2*jp+1]);
    #pragma unroll
    for(int k = 0; k < NDIM; k++)
      acc = ffma2(xk2[k], *(const u64t*)&sw[k*EMB + 2*jp], acc);
    float2 f = unpack2(acc);
    y[2*jp] = f.x; y[2*jp+1] = f.y;
    sum += f.x + f.y;
  }
  float mu = sum * (1.f/EMB);
  float vs = 0.f;
  #pragma unroll
  for(int j = 0; j < EMB; j++){ float d = y[j]-mu; vs += d*d; }
  float inv = rsqrtf(vs*(1.f/EMB) + LN_EPS);
  #pragma unroll
  for(int j = 0; j < EMB; j++){
    float v = (y[j]-mu)*inv*sg[j] + sbt[j];
    g_x[(size_t)n*EMB + j] = fmaxf(v, 0.f);
  }
}

// ---------------- edge MLP + 9 projections + fused CSR scatter (1 thread/edge) ----
__global__ void k_edge_mlp(const float* __restrict__ EA, const float* __restrict__ w,
                           const float* __restrict__ b, const float* __restrict__ g,
                           const float* __restrict__ beta, const float* __restrict__ gat_a,
                           const float* __restrict__ out_a){
  __shared__ float sw[EADIM*EMB];
  __shared__ float sb[EMB], sg[EMB], sbt[EMB];
  __shared__ float sa[9][EMB];
  for(int i = threadIdx.x; i < EADIM*EMB; i += blockDim.x) sw[i] = w[i];
  for(int i = threadIdx.x; i < EMB; i += blockDim.x){ sb[i]=b[i]; sg[i]=g[i]; sbt[i]=beta[i]; }
  for(int i = threadIdx.x; i < 9*EMB; i += blockDim.x){
    int p = i/EMB, j = i%EMB;
    sa[p][j] = (p < 8) ? gat_a[p*192 + 128 + j] : out_a[128 + j];
  }
  __syncthreads();
  int e = blockIdx.x*blockDim.x + threadIdx.x;
  if(e >= NEDGES) return;
  const float4* pe = (const float4*)(EA + (size_t)e*EADIM);
  float4 a0 = pe[0], a1 = pe[1];
  float xin[EADIM] = {a0.x,a0.y,a0.z,a0.w,a1.x,a1.y,a1.z,a1.w};
  u64t xk2[EADIM];
  #pragma unroll
  for(int k = 0; k < EADIM; k++) xk2[k] = pack2(xin[k], xin[k]);
  float y[EMB]; float sum = 0.f;
  #pragma unroll
  for(int jp = 0; jp < EMB/2; jp++){
    u64t acc = pack2(sb[2*jp], sb[2*jp+1]);
    #pragma unroll
    for(int k = 0; k < EADIM; k++)
      acc = ffma2(xk2[k], *(const u64t*)&sw[k*EMB + 2*jp], acc);
    float2 f = unpack2(acc);
    y[2*jp] = f.x; y[2*jp+1] = f.y;
    sum += f.x + f.y;
  }
  float mu = sum*(1.f/EMB);
  float vs = 0.f;
  #pragma unroll
  for(int j = 0; j < EMB; j++){ float d = y[j]-mu; vs += d*d; }
  float inv = rsqrtf(vs*(1.f/EMB) + LN_EPS);
  u64t y2[EMB/2];
  #pragma unroll
  for(int j = 0; j < EMB; j += 2){
    float v0 = fmaxf((y[j]-mu)*inv*sg[j] + sbt[j], 0.f);
    float v1 = fmaxf((y[j+1]-mu)*inv*sg[j+1] + sbt[j+1], 0.f);
    y2[j/2] = pack2(v0, v1);
  }
  float pr[9];
  #pragma unroll
  for(int p = 0; p < 9; p++){
    u64t acc = 0;
    #pragma unroll
    for(int jp = 0; jp < EMB/2; jp++)
      acc = ffma2(y2[jp], *(const u64t*)&sa[p][2*jp], acc);
    float2 f = unpack2(acc);
    pr[p] = f.x + f.y;
  }
  int s = g_src[e];
  int pos = atomicAdd(&g_cur[s], 1);
  g_tgtc[pos] = g_tgt[e];
  __half2 q0 = __floats2half2_rn(pr[0], pr[1]);
  __half2 q1 = __floats2half2_rn(pr[2], pr[3]);
  __half2 q2 = __floats2half2_rn(pr[4], pr[5]);
  __half2 q3 = __floats2half2_rn(pr[6], pr[7]);
  uint4 st;
  st.x = *(unsigned*)&q0; st.y = *(unsigned*)&q1;
  st.z = *(unsigned*)&q2; st.w = *(unsigned*)&q3;
  *(uint4*)&g_eap16[(size_t)pos*8] = st;
  g_eap2[pos] = pr[8];
}

// -------- all-heads h = x @ W -> e4m3 interleaved [n][head][64] -----
__global__ void k_head_h(const float* __restrict__ gat_W, const float* __restrict__ gat_a){
  __shared__ float sx[NPB*EMB];   // 20KB
  __shared__ float sw[EMB*DOUT];  // 16KB
  int n0 = blockIdx.x*NPB;
  int t = threadIdx.x;
  const float4* px = (const float4*)(g_x + (size_t)n0*EMB);
  #pragma unroll
  for(int i = 0; i < 5; i++)
    ((float4*)sx)[t + 256*i] = px[t + 256*i];
  int nn = t >> 4;
  int j0 = (t & 15)*4;
  for(int head = 0; head < NHEADS; head++){
    __syncthreads();
    const float* W = gat_W + (size_t)head*EMB*DOUT;
    #pragma unroll
    for(int i = 0; i < 4; i++)
      ((float4*)sw)[t + 256*i] = ((const float4*)W)[t + 256*i];
    __syncthreads();
    const float* a = gat_a + head*192;
    float aj0 = a[j0],    aj1 = a[j0+1],    aj2 = a[j0+2],    aj3 = a[j0+3];
    float bj0 = a[64+j0], bj1 = a[64+j0+1], bj2 = a[64+j0+2], bj3 = a[64+j0+3];
    #pragma unroll
    for(int g = 0; g < 5; g++){
      u64t acc01 = 0, acc23 = 0;
      const float* xr = &sx[(g*16 + nn)*EMB];
      #pragma unroll
      for(int k = 0; k < EMB; k++){
        float xv = xr[k];
        u64t xv2 = pack2(xv, xv);
        acc01 = ffma2(xv2, *(const u64t*)&sw[k*DOUT + j0],     acc01);
        acc23 = ffma2(xv2, *(const u64t*)&sw[k*DOUT + j0 + 2], acc23);
      }
      float2 f01 = unpack2(acc01), f23 = unpack2(acc23);
      float4 acc = {f01.x, f01.y, f23.x, f23.y};
      int n = n0 + g*16 + nn;
      unsigned short p01 = f2_fp8x2(acc.x, acc.y);
      unsigned short p23 = f2_fp8x2(acc.z, acc.w);
      unsigned pk = ((unsigned)p23 << 16) | (unsigned)p01;
      *(unsigned*)&g_h8[(size_t)n*512 + head*64 + j0] = pk;
      float ps = acc.x*aj0 + acc.y*aj1 + acc.z*aj2 + acc.w*aj3;
      float pt = acc.x*bj0 + acc.y*bj1 + acc.z*bj2 + acc.w*bj3;
      #pragma unroll
      for(int o = 8; o >= 1; o >>= 1){
        ps += __shfl_xor_sync(0xffffffffu, ps, o);
        pt += __shfl_xor_sync(0xffffffffu, pt, o);
      }
      if((t & 15) == 0){
        g_asrc8[n*8 + head] = ps;
        g_atgt8[n*8 + head] = pt;
      }
    }
  }
}

// ------- FUSED layer-1: 2 warps per node (4 heads each), fp8 gathers -------
__global__ void k_fagg1(){
  int gw = (blockIdx.x*blockDim.x + threadIdx.x) >> 5;
  int lane = threadIdx.x & 31;
  if(gw >= 2*NNODES) return;
  int n = gw >> 1;
  int grp = gw & 1;
  int hb = grp*4;
  int r0 = g_row[n], r1 = g_row[n+1];
  float asl = (lane < 4) ? g_asrc8[n*8 + hb + lane] : 0.f;
  int hsub = lane >> 3;
  float acc[8];
  #pragma unroll
  for(int i = 0; i < 8; i++) acc[i] = 0.f;
  float den = 0.f;
  int pos = r0;
  for(; pos + 1 < r1; pos += 2){
    int tg0 = g_tgtc[pos];
    int tg1 = g_tgtc[pos+1];
    const uint2* hp0 = (const uint2*)(g_h8 + (size_t)tg0*512 + grp*256);
    const uint2* hp1 = (const uint2*)(g_h8 + (size_t)tg1*512 + grp*256);
    uint2 va = hp0[lane];
    uint2 vb = hp1[lane];
    float e0 = 0.f, e1 = 0.f, t0 = 0.f, t1 = 0.f;
    if(lane < 4){
      e0 = __half2float(g_eap16[(size_t)pos*8 + hb + lane]);
      e1 = __half2float(g_eap16[(size_t)(pos+1)*8 + hb + lane]);
      t0 = g_atgt8[tg0*8 + hb + lane];
      t1 = g_atgt8[tg1*8 + hb + lane];
    }
    float ev0 = __expf(lrelu(asl + t0 + e0));
    float ev1 = __expf(lrelu(asl + t1 + e1));
    if(lane < 4) den += ev0 + ev1;
    float w0 = __shfl_sync(0xffffffffu, ev0, hsub);
    float w1 = __shfl_sync(0xffffffffu, ev1, hsub);
    #pragma unroll
    for(int q = 0; q < 2; q++){
      unsigned ua = q ? va.y : va.x;
      unsigned ub = q ? vb.y : vb.x;
      float2 fa0 = fp8x2_f2(ua & 0xffffu);
      float2 fa1 = fp8x2_f2(ua >> 16);
      float2 fb0 = fp8x2_f2(ub & 0xffffu);
      float2 fb1 = fp8x2_f2(ub >> 16);
      acc[4*q]   += w0*fa0.x + w1*fb0.x;
      acc[4*q+1] += w0*fa0.y + w1*fb0.y;
      acc[4*q+2] += w0*fa1.x + w1*fb1.x;
      acc[4*q+3] += w0*fa1.y + w1*fb1.y;
    }
  }
  if(pos < r1){
    int tg = g_tgtc[pos];
    const uint2* hp = (const uint2*)(g_h8 + (size_t)tg*512 + grp*256);
    uint2 va = hp[lane];
    float e0 = 0.f, t0 = 0.f;
    if(lane < 4){
      e0 = __half2float(g_eap16[(size_t)pos*8 + hb + lane]);
      t0 = g_atgt8[tg*8 + hb + lane];
    }
    float ev = __expf(lrelu(asl + t0 + e0));
    if(lane < 4) den += ev;
    float w0 = __shfl_sync(0xffffffffu, ev, hsub);
    #pragma unroll
    for(int q = 0; q < 2; q++){
      unsigned ua = q ? va.y : va.x;
      float2 fa0 = fp8x2_f2(ua & 0xffffu);
      float2 fa1 = fp8x2_f2(ua >> 16);
      acc[4*q]   += w0*fa0.x;
      acc[4*q+1] += w0*fa0.y;
      acc[4*q+2] += w0*fa1.x;
      acc[4*q+3] += w0*fa1.y;
    }
  }
  float rd = 1.f/(den + 1e-16f);
  float rdm = __shfl_sync(0xffffffffu, rd, hsub);
  int hglob = hb + hsub;
  int jj = (lane & 7)*8;
  uint4 o; __half2* po = (__half2*)&o;
  #pragma unroll
  for(int q = 0; q < 4; q++){
    float v0 = eluf(eluf(acc[2*q]*rdm));
    float v1 = eluf(eluf(acc[2*q+1]*rdm));
    po[q] = __floats2half2_rn(v0, v1);
  }
  *(uint4*)&g_hph[((size_t)hglob*NNODES + n)*64 + jj] = o;
}

// ---------------- final layer h2 = hph_concat @ out_W (elu pre-applied) ------------
__global__ void k_out_h(const float* __restrict__ out_W, const float* __restrict__ out_a){
  __shared__ float sx[NPB*EMB];   // 20KB
  __shared__ float sw[EMB*DOUT];  // 16KB
  int n0 = blockIdx.x*NPB;
  int t = threadIdx.x;
  int nn = t >> 4;
  int j0 = (t & 15)*4;
  u64t a01[5], a23[5];
  #pragma unroll
  for(int g = 0; g < 5; g++){ a01[g] = 0; a23[g] = 0; }
  for(int c = 0; c < NHEADS; c++){
    __syncthreads();
    #pragma unroll
    for(int i = 0; i < 4; i++)
      ((float4*)sw)[t + 256*i] = ((const float4*)(out_W + (size_t)c*EMB*DOUT))[t + 256*i];
    const uint2* hp = (const uint2*)(g_hph + ((size_t)c*NNODES + n0)*64);
    #pragma unroll
    for(int i = 0; i < 5; i++){
      uint2 u = hp[t + 256*i];
      float2 fa = __half22float2(*(const __half2*)&u.x);
      float2 fb = __half22float2(*(const __half2*)&u.y);
      float4 xv4 = {fa.x, fa.y, fb.x, fb.y};
      ((float4*)sx)[t + 256*i] = xv4;
    }
    __syncthreads();
    #pragma unroll
    for(int k = 0; k < EMB; k++){
      u64t w01 = *(const u64t*)&sw[k*DOUT + j0];
      u64t w23 = *(const u64t*)&sw[k*DOUT + j0 + 2];
      #pragma unroll
      for(int g = 0; g < 5; g++){
        float xv = sx[(g*16 + nn)*EMB + k];
        u64t xv2 = pack2(xv, xv);
        a01[g] = ffma2(xv2, w01, a01[g]);
        a23[g] = ffma2(xv2, w23, a23[g]);
      }
    }
  }
  #pragma unroll
  for(int g = 0; g < 5; g++){
    float2 f01 = unpack2(a01[g]), f23 = unpack2(a23[g]);
    float4 acc = {f01.x, f01.y, f23.x, f23.y};
    int n = n0 + g*16 + nn;
    __half2 lo = __floats2half2_rn(acc.x, acc.y);
    __half2 hi = __floats2half2_rn(acc.z, acc.w);
    uint2 u; u.x = *(unsigned*)&lo; u.y = *(unsigned*)&hi;
    *(uint2*)&g_h2h[(size_t)n*64 + j0] = u;
    float ps = acc.x*out_a[j0] + acc.y*out_a[j0+1] + acc.z*out_a[j0+2] + acc.w*out_a[j0+3];
    float pt = acc.x*out_a[64+j0] + acc.y*out_a[64+j0+1] + acc.z*out_a[64+j0+2] + acc.w*out_a[64+j0+3];
    #pragma unroll
    for(int o = 8; o >= 1; o >>= 1){
      ps += __shfl_xor_sync(0xffffffffu, ps, o);
      pt += __shfl_xor_sync(0xffffffffu, pt, o);
    }
    if((t & 15) == 0){
      g_asrc2[n] = ps;
      g_atgt2[n] = pt;
    }
  }
}

// -------- fused layer-2 aggregation + elu + log_softmax (writes d_out directly) ----
__global__ void k_fagg2ls(float* __restrict__ out){
  int warp = (blockIdx.x*blockDim.x + threadIdx.x) >> 5;
  int lane = threadIdx.x & 31;
  if(warp >= NNODES) return;
  int n = warp;
  int r0 = g_row[n], r1 = g_row[n+1];
  float as2 = g_asrc2[n];
  float ax = 0.f, ay = 0.f, den = 0.f;
  int pos = r0;
  for(; pos + 1 < r1; pos += 2){
    int tg0 = g_tgtc[pos];
    int tg1 = g_tgtc[pos+1];
    float2 v0 = __half22float2(((const __half2*)(g_h2h + (size_t)tg0*DOUT))[lane]);
    float2 v1 = __half22float2(((const __half2*)(g_h2h + (size_t)tg1*DOUT))[lane]);
    float at0 = g_atgt2[tg0];
    float at1 = g_atgt2[tg1];
    float ep0 = g_eap2[pos];
    float ep1 = g_eap2[pos+1];
    float ev0 = __expf(lrelu(as2 + at0 + ep0));
    float ev1 = __expf(lrelu(as2 + at1 + ep1));
    den += ev0 + ev1;
    ax += ev0*v0.x + ev1*v1.x;
    ay += ev0*v0.y + ev1*v1.y;
  }
  if(pos < r1){
    int tg = g_tgtc[pos];
    float2 v = __half22float2(((const __half2*)(g_h2h + (size_t)tg*DOUT))[lane]);
    float ev = __expf(lrelu(as2 + g_atgt2[tg] + g_eap2[pos]));
    den += ev;
    ax += ev*v.x; ay += ev*v.y;
  }
  float rd = 1.f/(den + 1e-16f);
  float v0 = eluf(ax*rd);
  float v1 = eluf(ay*rd);
  float m = fmaxf(v0, v1);
  #pragma unroll
  for(int o = 16; o >= 1; o >>= 1) m = fmaxf(m, __shfl_xor_sync(0xffffffffu, m, o));
  float s = __expf(v0 - m) + __expf(v1 - m);
  #pragma unroll
  for(int o = 16; o >= 1; o >>= 1) s += __shfl_xor_sync(0xffffffffu, s, o);
  float l = logf(s);
  float2 o2 = {v0 - m - l, v1 - m - l};
  ((float2*)(out + (size_t)n*DOUT))[lane] = o2;
}

// ---------------- launcher ----------------
extern "C" void kernel_launch(void* const* d_in, const int* in_sizes, int n_in,
                              void* d_out, int out_size){
  const float *X=0, *EA=0, *w_node=0, *w_edge=0, *gatW=0, *gata=0, *outW=0, *outa=0;
  const void* ei = 0;
  const float* v64[8]; int n64 = 0; int nbig = 0;
  for(int i = 0; i < n_in; i++){
    switch(in_sizes[i]){
      case 800000:  X    = (const float*)d_in[i]; break;
      case 8000000: EA   = (const float*)d_in[i]; break;
      case 2000000: ei   = d_in[i]; break;
      case 1024:    w_node = (const float*)d_in[i]; break;
      case 512:     w_edge = (const float*)d_in[i]; break;
      case 1536:    gata = (const float*)d_in[i]; break;
      case 192:     outa = (const float*)d_in[i]; break;
      case 32768:   if(nbig++ == 0) gatW = (const float*)d_in[i];
                    else            outW = (const float*)d_in[i];
                    break;
      case 64:      if(n64 < 8) v64[n64++] = (const float*)d_in[i]; break;
      default: break;
    }
  }
  const float* b_node = v64[0]; const float* g_node = v64[1]; const float* beta_node = v64[2];
  const float* b_edge = v64[3]; const float* g_edge = v64[4]; const float* beta_edge = v64[5];

  // fork node-side chain (node_mlp -> head_h) onto stream s2
  cudaEventRecord(g_sh.e0, 0);
  cudaStreamWaitEvent(g_sh.s2, g_sh.e0, 0);
  k_node_mlp<<<(NNODES + 255)/256, 256, 0, g_sh.s2>>>(X, w_node, b_node, g_node, beta_node);
  k_head_h<<<NNODES/NPB, 256, 0, g_sh.s2>>>(gatW, gata);
  cudaEventRecord(g_sh.e1, g_sh.s2);

  // edge-side chain on default stream: CSR build + edge MLP
  k_init<<<(NNODES + 255)/256, 256>>>(ei);
  k_convert<<<(NEDGES + 255)/256, 256>>>(ei);
  k_scan1<<<SCANB, 1024>>>();
  k_scan2<<<1, 32>>>();
  k_scan3<<<SCANB, 1024>>>();
  k_edge_mlp<<<(NEDGES + 127)/128, 128>>>(EA, w_edge, b_edge, g_edge, beta_edge, gata, outa);

  // join: fagg1 needs both chains
  cudaStreamWaitEvent(0, g_sh.e1, 0);

  // layer 1: fused softmax-aggregation, 2 warps per node, fp8 gathers
  k_fagg1<<<(2*NNODES*32 + 255)/256, 256>>>();

  // layer 2
  k_out_h<<<NNODES/NPB, 256>>>(outW, outa);
  k_fagg2ls<<<(NNODES*32 + 255)/256, 256>>>((float*)d_out);
}

// round 16
// speedup vs baseline: 1.0508x; 1.0301x over previous
#include <cuda_runtime.h>
#include <cuda_fp16.h>
#include <math.h>

#define NNODES 50000
#define NEDGES 1000000
#define NDIM   16
#define EMB    64
#define DOUT   64
#define NHEADS 8
#define EADIM  8
#define SLOPE  0.01f
#define LN_EPS 1e-5f
#define SCANB  49    // ceil(50000/1024)
#define NPB    80    // nodes per block in GEMM kernels (50000 = 625*80)

// ---------------- scratch ----------------
__device__ __align__(128) float  g_x[(size_t)NNODES*EMB];
__device__ __align__(128) __half g_eap16[(size_t)NEDGES*8];  // projections -> exp(score), fp16
__device__ __align__(128) float  g_eap2[NEDGES];
__device__ __align__(128) unsigned char g_h8[(size_t)NNODES*512]; // h [n][head][64] e4m3
__device__ __align__(128) __half g_hph[(size_t)NHEADS*NNODES*DOUT]; // stores elu(elu(hp))
__device__ __align__(128) __half g_h2h[(size_t)NNODES*DOUT];
__device__ __align__(128) float  g_asrc8[NNODES*8];
__device__ __align__(128) float  g_atgt8[NNODES*8];
__device__ __align__(128) float  g_asrc2[NNODES];
__device__ __align__(128) float  g_atgt2[NNODES];
__device__ __align__(128) int g_src[NEDGES];
__device__ __align__(128) int g_tgt[NEDGES];
__device__ __align__(128) int g_tgtc[NEDGES];
__device__ __align__(128) int g_row[NNODES+1];
__device__ __align__(128) int g_cur[NNODES];
__device__ __align__(128) int g_cnt[NNODES];
__device__ __align__(128) int g_part[64];
__device__ int g_flag;

__device__ __forceinline__ float eluf(float x){ return x > 0.f ? x : expm1f(x); }
__device__ __forceinline__ float lrelu(float x){ return x >= 0.f ? x : SLOPE * x; }

typedef unsigned long long u64t;
__device__ __forceinline__ u64t pack2(float lo, float hi){
  u64t r; asm("mov.b64 %0, {%1,%2};" : "=l"(r) : "f"(lo), "f"(hi)); return r;
}
__device__ __forceinline__ u64t ffma2(u64t a, u64t b, u64t c){
  u64t d; asm("fma.rn.f32x2 %0, %1, %2, %3;" : "=l"(d) : "l"(a), "l"(b), "l"(c)); return d;
}
__device__ __forceinline__ float2 unpack2(u64t v){
  float2 f; asm("mov.b64 {%0,%1}, %2;" : "=f"(f.x), "=f"(f.y) : "l"(v)); return f;
}
// fp8 e4m3 pair -> float2 (HW converter)
__device__ __forceinline__ float2 fp8x2_f2(unsigned v16){
  unsigned r; asm("cvt.rn.f16x2.e4m3x2 %0, %1;" : "=r"(r) : "h"((unsigned short)v16));
  return __half22float2(*(__half2*)&r);
}
// two floats -> e4m3 pair (lo = a, hi = b)
__device__ __forceinline__ unsigned short f2_fp8x2(float lo, float hi){
  unsigned short d;
  asm("cvt.rn.satfinite.e4m3x2.f32 %0, %1, %2;" : "=h"(d) : "f"(hi), "f"(lo));
  return d;
}

// ---------------- streams for phase overlap ----------------
struct StreamsHolder {
  cudaStream_t s2;
  cudaEvent_t e0, e1;
  StreamsHolder(){
    cudaStreamCreateWithFlags(&s2, cudaStreamNonBlocking);
    cudaEventCreateWithFlags(&e0, cudaEventDisableTiming);
    cudaEventCreateWithFlags(&e1, cudaEventDisableTiming);
  }
};
static StreamsHolder g_sh;

// ---------------- init: dtype detect + zero counters ----------------
__global__ void k_init(const void* ei){
  int i = blockIdx.x*blockDim.x + threadIdx.x;
  if(i < NNODES) g_cnt[i] = 0;
  if(i == 0){
    const long long* p = (const long long*)ei;
    int is64 = 1;
    for(int k = 0; k < 64; k++){
      long long v = p[k];
      if(v < 0 || v >= 4294967296LL) is64 = 0;
    }
    g_flag = is64;
  }
}

__global__ void k_convert(const void* ei){
  int e = blockIdx.x*blockDim.x + threadIdx.x;
  if(e >= NEDGES) return;
  int s, t;
  if(g_flag){
    const long long* p = (const long long*)ei;
    s = (int)p[e]; t = (int)p[NEDGES + e];
  } else {
    const int* p = (const int*)ei;
    s = p[e]; t = p[NEDGES + e];
  }
  g_src[e] = s; g_tgt[e] = t;
  atomicAdd(&g_cnt[s], 1);
}

// ---------------- parallel scan (3 phases) ----------------
__global__ void k_scan1(){
  __shared__ int swarp[32];
  int i = blockIdx.x*1024 + threadIdx.x;
  int lane = threadIdx.x & 31, wid = threadIdx.x >> 5;
  int v = (i < NNODES) ? g_cnt[i] : 0;
  int x = v;
  #pragma unroll
  for(int o = 1; o < 32; o <<= 1){
    int y = __shfl_up_sync(0xffffffffu, x, o);
    if(lane >= o) x += y;
  }
  if(lane == 31) swarp[wid] = x;
  __syncthreads();
  if(wid == 0){
    int s = swarp[lane];
    #pragma unroll
    for(int o = 1; o < 32; o <<= 1){
      int y = __shfl_up_sync(0xffffffffu, s, o);
      if(lane >= o) s += y;
    }
    swarp[lane] = s;
  }
  __syncthreads();
  int base = wid ? swarp[wid-1] : 0;
  int incl = base + x;
  if(i < NNODES) g_row[i] = incl - v;
  if(threadIdx.x == 1023) g_part[blockIdx.x] = incl;
}

__global__ void k_scan2(){
  if(threadIdx.x == 0){
    int s = 0;
    for(int i = 0; i < SCANB; i++){ int v = g_part[i]; g_part[i] = s; s += v; }
  }
}

__global__ void k_scan3(){
  int i = blockIdx.x*1024 + threadIdx.x;
  if(i < NNODES){
    int r = g_row[i] + g_part[blockIdx.x];
    g_row[i] = r; g_cur[i] = r;
  }
  if(i == 0) g_row[NNODES] = NEDGES;
}

// ---------------- node MLP ----------------
__global__ void k_node_mlp(const float* __restrict__ X, const float* __restrict__ w,
                           const float* __restrict__ b, const float* __restrict__ g,
                           const float* __restrict__ beta){
  __shared__ float sw[NDIM*EMB];
  __shared__ float sb[EMB], sg[EMB], sbt[EMB];
  for(int i = threadIdx.x; i < NDIM*EMB; i += blockDim.x) sw[i] = w[i];
  for(int i = threadIdx.x; i < EMB; i += blockDim.x){ sb[i]=b[i]; sg[i]=g[i]; sbt[i]=beta[i]; }
  __syncthreads();
  int n = blockIdx.x*blockDim.x + threadIdx.x;
  if(n >= NNODES) return;
  float xin[NDIM];
  const float4* px = (const float4*)(X + (size_t)n*NDIM);
  #pragma unroll
  for(int q = 0; q < 4; q++){
    float4 v = px[q];
    xin[q*4+0]=v.x; xin[q*4+1]=v.y; xin[q*4+2]=v.z; xin[q*4+3]=v.w;
  }
  u64t xk2[NDIM];
  #pragma unroll
  for(int k = 0; k < NDIM; k++) xk2[k] = pack2(xin[k], xin[k]);
  float y[EMB]; float sum = 0.f;
  #pragma unroll
  for(int jp = 0; jp < EMB/2; jp++){
    u64t acc = pack2(sb[2*jp], sb[2*jp+1]);
    #pragma unroll
    for(int k = 0; k < NDIM; k++)
      acc = ffma2(xk2[k], *(const u64t*)&sw[k*EMB + 2*jp], acc);
    float2 f = unpack2(acc);
    y[2*jp] = f.x; y[2*jp+1] = f.y;
    sum += f.x + f.y;
  }
  float mu = sum * (1.f/EMB);
  float vs = 0.f;
  #pragma unroll
  for(int j = 0; j < EMB; j++){ float d = y[j]-mu; vs += d*d; }
  float inv = rsqrtf(vs*(1.f/EMB) + LN_EPS);
  #pragma unroll
  for(int j = 0; j < EMB; j++){
    float v = (y[j]-mu)*inv*sg[j] + sbt[j];
    g_x[(size_t)n*EMB + j] = fmaxf(v, 0.f);
  }
}

// ---------------- edge MLP + 9 projections + fused CSR scatter (1 thread/edge) ----
__global__ void k_edge_mlp(const float* __restrict__ EA, const float* __restrict__ w,
                           const float* __restrict__ b, const float* __restrict__ g,
                           const float* __restrict__ beta, const float* __restrict__ gat_a,
                           const float* __restrict__ out_a){
  __shared__ float sw[EADIM*EMB];
  __shared__ float sb[EMB], sg[EMB], sbt[EMB];
  __shared__ float sa[9][EMB];
  for(int i = threadIdx.x; i < EADIM*EMB; i += blockDim.x) sw[i] = w[i];
  for(int i = threadIdx.x; i < EMB; i += blockDim.x){ sb[i]=b[i]; sg[i]=g[i]; sbt[i]=beta[i]; }
  for(int i = threadIdx.x; i < 9*EMB; i += blockDim.x){
    int p = i/EMB, j = i%EMB;
    sa[p][j] = (p < 8) ? gat_a[p*192 + 128 + j] : out_a[128 + j];
  }
  __syncthreads();
  int e = blockIdx.x*blockDim.x + threadIdx.x;
  if(e >= NEDGES) return;
  const float4* pe = (const float4*)(EA + (size_t)e*EADIM);
  float4 a0 = pe[0], a1 = pe[1];
  float xin[EADIM] = {a0.x,a0.y,a0.z,a0.w,a1.x,a1.y,a1.z,a1.w};
  u64t xk2[EADIM];
  #pragma unroll
  for(int k = 0; k < EADIM; k++) xk2[k] = pack2(xin[k], xin[k]);
  float y[EMB]; float sum = 0.f;
  #pragma unroll
  for(int jp = 0; jp < EMB/2; jp++){
    u64t acc = pack2(sb[2*jp], sb[2*jp+1]);
    #pragma unroll
    for(int k = 0; k < EADIM; k++)
      acc = ffma2(xk2[k], *(const u64t*)&sw[k*EMB + 2*jp], acc);
    float2 f = unpack2(acc);
    y[2*jp] = f.x; y[2*jp+1] = f.y;
    sum += f.x + f.y;
  }
  float mu = sum*(1.f/EMB);
  float vs = 0.f;
  #pragma unroll
  for(int j = 0; j < EMB; j++){ float d = y[j]-mu; vs += d*d; }
  float inv = rsqrtf(vs*(1.f/EMB) + LN_EPS);
  u64t y2[EMB/2];
  #pragma unroll
  for(int j = 0; j < EMB; j += 2){
    float v0 = fmaxf((y[j]-mu)*inv*sg[j] + sbt[j], 0.f);
    float v1 = fmaxf((y[j+1]-mu)*inv*sg[j+1] + sbt[j+1], 0.f);
    y2[j/2] = pack2(v0, v1);
  }
  float pr[9];
  #pragma unroll
  for(int p = 0; p < 9; p++){
    u64t acc = 0;
    #pragma unroll
    for(int jp = 0; jp < EMB/2; jp++)
      acc = ffma2(y2[jp], *(const u64t*)&sa[p][2*jp], acc);
    float2 f = unpack2(acc);
    pr[p] = f.x + f.y;
  }
  int s = g_src[e];
  int pos = atomicAdd(&g_cur[s], 1);
  g_tgtc[pos] = g_tgt[e];
  __half2 q0 = __floats2half2_rn(pr[0], pr[1]);
  __half2 q1 = __floats2half2_rn(pr[2], pr[3]);
  __half2 q2 = __floats2half2_rn(pr[4], pr[5]);
  __half2 q3 = __floats2half2_rn(pr[6], pr[7]);
  uint4 st;
  st.x = *(unsigned*)&q0; st.y = *(unsigned*)&q1;
  st.z = *(unsigned*)&q2; st.w = *(unsigned*)&q3;
  *(uint4*)&g_eap16[(size_t)pos*8] = st;
  g_eap2[pos] = pr[8];
}

// -------- all-heads h = x @ W -> e4m3 interleaved [n][head][64] -----
__global__ void k_head_h(const float* __restrict__ gat_W, const float* __restrict__ gat_a){
  __shared__ float sx[NPB*EMB];   // 20KB
  __shared__ float sw[EMB*DOUT];  // 16KB
  int n0 = blockIdx.x*NPB;
  int t = threadIdx.x;
  const float4* px = (const float4*)(g_x + (size_t)n0*EMB);
  #pragma unroll
  for(int i = 0; i < 5; i++)
    ((float4*)sx)[t + 256*i] = px[t + 256*i];
  int nn = t >> 4;
  int j0 = (t & 15)*4;
  for(int head = 0; head < NHEADS; head++){
    __syncthreads();
    const float* W = gat_W + (size_t)head*EMB*DOUT;
    #pragma unroll
    for(int i = 0; i < 4; i++)
      ((float4*)sw)[t + 256*i] = ((const float4*)W)[t + 256*i];
    __syncthreads();
    const float* a = gat_a + head*192;
    float aj0 = a[j0],    aj1 = a[j0+1],    aj2 = a[j0+2],    aj3 = a[j0+3];
    float bj0 = a[64+j0], bj1 = a[64+j0+1], bj2 = a[64+j0+2], bj3 = a[64+j0+3];
    #pragma unroll
    for(int g = 0; g < 5; g++){
      u64t acc01 = 0, acc23 = 0;
      const float* xr = &sx[(g*16 + nn)*EMB];
      #pragma unroll
      for(int k = 0; k < EMB; k++){
        float xv = xr[k];
        u64t xv2 = pack2(xv, xv);
        acc01 = ffma2(xv2, *(const u64t*)&sw[k*DOUT + j0],     acc01);
        acc23 = ffma2(xv2, *(const u64t*)&sw[k*DOUT + j0 + 2], acc23);
      }
      float2 f01 = unpack2(acc01), f23 = unpack2(acc23);
      float4 acc = {f01.x, f01.y, f23.x, f23.y};
      int n = n0 + g*16 + nn;
      unsigned short p01 = f2_fp8x2(acc.x, acc.y);
      unsigned short p23 = f2_fp8x2(acc.z, acc.w);
      unsigned pk = ((unsigned)p23 << 16) | (unsigned)p01;
      *(unsigned*)&g_h8[(size_t)n*512 + head*64 + j0] = pk;
      float ps = acc.x*aj0 + acc.y*aj1 + acc.z*aj2 + acc.w*aj3;
      float pt = acc.x*bj0 + acc.y*bj1 + acc.z*bj2 + acc.w*bj3;
      #pragma unroll
      for(int o = 8; o >= 1; o >>= 1){
        ps += __shfl_xor_sync(0xffffffffu, ps, o);
        pt += __shfl_xor_sync(0xffffffffu, pt, o);
      }
      if((t & 15) == 0){
        g_asrc8[n*8 + head] = ps;
        g_atgt8[n*8 + head] = pt;
      }
    }
  }
}

// ------- NEW: per-edge exp(score) precompute (warp per node, lane per edge) -------
// overwrites g_eap16[pos][0..7] with exp(lrelu(asrc[n]+atgt[tgt]+eap)) per head, fp16
__global__ void k_ev(){
  int warp = (blockIdx.x*blockDim.x + threadIdx.x) >> 5;
  int lane = threadIdx.x & 31;
  if(warp >= NNODES) return;
  int n = warp;
  int r0 = g_row[n], r1 = g_row[n+1];
  float4 as0 = *(const float4*)&g_asrc8[n*8];
  float4 as1 = *(const float4*)&g_asrc8[n*8+4];
  for(int pos = r0 + lane; pos < r1; pos += 32){
    int tg = g_tgtc[pos];
    float4 t0 = *(const float4*)&g_atgt8[tg*8];
    float4 t1 = *(const float4*)&g_atgt8[tg*8+4];
    uint4 e = *(const uint4*)&g_eap16[(size_t)pos*8];
    float2 e0 = __half22float2(*(const __half2*)&e.x);
    float2 e1 = __half22float2(*(const __half2*)&e.y);
    float2 e2 = __half22float2(*(const __half2*)&e.z);
    float2 e3 = __half22float2(*(const __half2*)&e.w);
    float v0 = __expf(lrelu(as0.x + t0.x + e0.x));
    float v1 = __expf(lrelu(as0.y + t0.y + e0.y));
    float v2 = __expf(lrelu(as0.z + t0.z + e1.x));
    float v3 = __expf(lrelu(as0.w + t0.w + e1.y));
    float v4 = __expf(lrelu(as1.x + t1.x + e2.x));
    float v5 = __expf(lrelu(as1.y + t1.y + e2.y));
    float v6 = __expf(lrelu(as1.z + t1.z + e3.x));
    float v7 = __expf(lrelu(as1.w + t1.w + e3.y));
    __half2 h0 = __floats2half2_rn(v0, v1);
    __half2 h1 = __floats2half2_rn(v2, v3);
    __half2 h2 = __floats2half2_rn(v4, v5);
    __half2 h3 = __floats2half2_rn(v6, v7);
    uint4 st;
    st.x = *(unsigned*)&h0; st.y = *(unsigned*)&h1;
    st.z = *(unsigned*)&h2; st.w = *(unsigned*)&h3;
    *(uint4*)&g_eap16[(size_t)pos*8] = st;
  }
}

// ------- FUSED layer-1: 2 warps per node (4 heads each), fp8 gathers, lean loop -------
// scores are precomputed (k_ev): no shfl, no exp, no random atgt gathers here
__global__ void k_fagg1(){
  int gw = (blockIdx.x*blockDim.x + threadIdx.x) >> 5;
  int lane = threadIdx.x & 31;
  if(gw >= 2*NNODES) return;
  int n = gw >> 1;
  int grp = gw & 1;
  int hglob = grp*4 + (lane >> 3);
  int r0 = g_row[n], r1 = g_row[n+1];
  float acc[8];
  #pragma unroll
  for(int i = 0; i < 8; i++) acc[i] = 0.f;
  float den = 0.f;
  int pos = r0;
  for(; pos + 1 < r1; pos += 2){
    int tg0 = g_tgtc[pos];
    int tg1 = g_tgtc[pos+1];
    uint2 va = *(const uint2*)(g_h8 + (size_t)tg0*512 + grp*256 + lane*8);
    uint2 vb = *(const uint2*)(g_h8 + (size_t)tg1*512 + grp*256 + lane*8);
    float w0 = __half2float(g_eap16[(size_t)pos*8 + hglob]);
    float w1 = __half2float(g_eap16[(size_t)(pos+1)*8 + hglob]);
    den += w0 + w1;
    #pragma unroll
    for(int q = 0; q < 2; q++){
      unsigned ua = q ? va.y : va.x;
      unsigned ub = q ? vb.y : vb.x;
      float2 fa0 = fp8x2_f2(ua & 0xffffu);
      float2 fa1 = fp8x2_f2(ua >> 16);
      float2 fb0 = fp8x2_f2(ub & 0xffffu);
      float2 fb1 = fp8x2_f2(ub >> 16);
      acc[4*q]   += w0*fa0.x + w1*fb0.x;
      acc[4*q+1] += w0*fa0.y + w1*fb0.y;
      acc[4*q+2] += w0*fa1.x + w1*fb1.x;
      acc[4*q+3] += w0*fa1.y + w1*fb1.y;
    }
  }
  if(pos < r1){
    int tg = g_tgtc[pos];
    uint2 va = *(const uint2*)(g_h8 + (size_t)tg*512 + grp*256 + lane*8);
    float w0 = __half2float(g_eap16[(size_t)pos*8 + hglob]);
    den += w0;
    #pragma unroll
    for(int q = 0; q < 2; q++){
      unsigned ua = q ? va.y : va.x;
      float2 fa0 = fp8x2_f2(ua & 0xffffu);
      float2 fa1 = fp8x2_f2(ua >> 16);
      acc[4*q]   += w0*fa0.x;
      acc[4*q+1] += w0*fa0.y;
      acc[4*q+2] += w0*fa1.x;
      acc[4*q+3] += w0*fa1.y;
    }
  }
  float rdm = 1.f/(den + 1e-16f);   // identical across each 8-lane head group
  int jj = (lane & 7)*8;
  uint4 o; __half2* po = (__half2*)&o;
  #pragma unroll
  for(int q = 0; q < 4; q++){
    float v0 = eluf(eluf(acc[2*q]*rdm));
    float v1 = eluf(eluf(acc[2*q+1]*rdm));
    po[q] = __floats2half2_rn(v0, v1);
  }
  *(uint4*)&g_hph[((size_t)hglob*NNODES + n)*64 + jj] = o;
}

// ---------------- final layer h2 = hph_concat @ out_W (elu pre-applied) ------------
__global__ void k_out_h(const float* __restrict__ out_W, const float* __restrict__ out_a){
  __shared__ float sx[NPB*EMB];   // 20KB
  __shared__ float sw[EMB*DOUT];  // 16KB
  int n0 = blockIdx.x*NPB;
  int t = threadIdx.x;
  int nn = t >> 4;
  int j0 = (t & 15)*4;
  u64t a01[5], a23[5];
  #pragma unroll
  for(int g = 0; g < 5; g++){ a01[g] = 0; a23[g] = 0; }
  for(int c = 0; c < NHEADS; c++){
    __syncthreads();
    #pragma unroll
    for(int i = 0; i < 4; i++)
      ((float4*)sw)[t + 256*i] = ((const float4*)(out_W + (size_t)c*EMB*DOUT))[t + 256*i];
    const uint2* hp = (const uint2*)(g_hph + ((size_t)c*NNODES + n0)*64);
    #pragma unroll
    for(int i = 0; i < 5; i++){
      uint2 u = hp[t + 256*i];
      float2 fa = __half22float2(*(const __half2*)&u.x);
      float2 fb = __half22float2(*(const __half2*)&u.y);
      float4 xv4 = {fa.x, fa.y, fb.x, fb.y};
      ((float4*)sx)[t + 256*i] = xv4;
    }
    __syncthreads();
    #pragma unroll
    for(int k = 0; k < EMB; k++){
      u64t w01 = *(const u64t*)&sw[k*DOUT + j0];
      u64t w23 = *(const u64t*)&sw[k*DOUT + j0 + 2];
      #pragma unroll
      for(int g = 0; g < 5; g++){
        float xv = sx[(g*16 + nn)*EMB + k];
        u64t xv2 = pack2(xv, xv);
        a01[g] = ffma2(xv2, w01, a01[g]);
        a23[g] = ffma2(xv2, w23, a23[g]);
      }
    }
  }
  #pragma unroll
  for(int g = 0; g < 5; g++){
    float2 f01 = unpack2(a01[g]), f23 = unpack2(a23[g]);
    float4 acc = {f01.x, f01.y, f23.x, f23.y};
    int n = n0 + g*16 + nn;
    __half2 lo = __floats2half2_rn(acc.x, acc.y);
    __half2 hi = __floats2half2_rn(acc.z, acc.w);
    uint2 u; u.x = *(unsigned*)&lo; u.y = *(unsigned*)&hi;
    *(uint2*)&g_h2h[(size_t)n*64 + j0] = u;
    float ps = acc.x*out_a[j0] + acc.y*out_a[j0+1] + acc.z*out_a[j0+2] + acc.w*out_a[j0+3];
    float pt = acc.x*out_a[64+j0] + acc.y*out_a[64+j0+1] + acc.z*out_a[64+j0+2] + acc.w*out_a[64+j0+3];
    #pragma unroll
    for(int o = 8; o >= 1; o >>= 1){
      ps += __shfl_xor_sync(0xffffffffu, ps, o);
      pt += __shfl_xor_sync(0xffffffffu, pt, o);
    }
    if((t & 15) == 0){
      g_asrc2[n] = ps;
      g_atgt2[n] = pt;
    }
  }
}

// -------- fused layer-2 aggregation + elu + log_softmax (writes d_out directly) ----
__global__ void k_fagg2ls(float* __restrict__ out){
  int warp = (blockIdx.x*blockDim.x + threadIdx.x) >> 5;
  int lane = threadIdx.x & 31;
  if(warp >= NNODES) return;
  int n = warp;
  int r0 = g_row[n], r1 = g_row[n+1];
  float as2 = g_asrc2[n];
  float ax = 0.f, ay = 0.f, den = 0.f;
  int pos = r0;
  for(; pos + 1 < r1; pos += 2){
    int tg0 = g_tgtc[pos];
    int tg1 = g_tgtc[pos+1];
    float2 v0 = __half22float2(((const __half2*)(g_h2h + (size_t)tg0*DOUT))[lane]);
    float2 v1 = __half22float2(((const __half2*)(g_h2h + (size_t)tg1*DOUT))[lane]);
    float at0 = g_atgt2[tg0];
    float at1 = g_atgt2[tg1];
    float ep0 = g_eap2[pos];
    float ep1 = g_eap2[pos+1];
    float ev0 = __expf(lrelu(as2 + at0 + ep0));
    float ev1 = __expf(lrelu(as2 + at1 + ep1));
    den += ev0 + ev1;
    ax += ev0*v0.x + ev1*v1.x;
    ay += ev0*v0.y + ev1*v1.y;
  }
  if(pos < r1){
    int tg = g_tgtc[pos];
    float2 v = __half22float2(((const __half2*)(g_h2h + (size_t)tg*DOUT))[lane]);
    float ev = __expf(lrelu(as2 + g_atgt2[tg] + g_eap2[pos]));
    den += ev;
    ax += ev*v.x; ay += ev*v.y;
  }
  float rd = 1.f/(den + 1e-16f);
  float v0 = eluf(ax*rd);
  float v1 = eluf(ay*rd);
  float m = fmaxf(v0, v1);
  #pragma unroll
  for(int o = 16; o >= 1; o >>= 1) m = fmaxf(m, __shfl_xor_sync(0xffffffffu, m, o));
  float s = __expf(v0 - m) + __expf(v1 - m);
  #pragma unroll
  for(int o = 16; o >= 1; o >>= 1) s += __shfl_xor_sync(0xffffffffu, s, o);
  float l = logf(s);
  float2 o2 = {v0 - m - l, v1 - m - l};
  ((float2*)(out + (size_t)n*DOUT))[lane] = o2;
}

// ---------------- launcher ----------------
extern "C" void kernel_launch(void* const* d_in, const int* in_sizes, int n_in,
                              void* d_out, int out_size){
  const float *X=0, *EA=0, *w_node=0, *w_edge=0, *gatW=0, *gata=0, *outW=0, *outa=0;
  const void* ei = 0;
  const float* v64[8]; int n64 = 0; int nbig = 0;
  for(int i = 0; i < n_in; i++){
    switch(in_sizes[i]){
      case 800000:  X    = (const float*)d_in[i]; break;
      case 8000000: EA   = (const float*)d_in[i]; break;
      case 2000000: ei   = d_in[i]; break;
      case 1024:    w_node = (const float*)d_in[i]; break;
      case 512:     w_edge = (const float*)d_in[i]; break;
      case 1536:    gata = (const float*)d_in[i]; break;
      case 192:     outa = (const float*)d_in[i]; break;
      case 32768:   if(nbig++ == 0) gatW = (const float*)d_in[i];
                    else            outW = (const float*)d_in[i];
                    break;
      case 64:      if(n64 < 8) v64[n64++] = (const float*)d_in[i]; break;
      default: break;
    }
  }
  const float* b_node = v64[0]; const float* g_node = v64[1]; const float* beta_node = v64[2];
  const float* b_edge = v64[3]; const float* g_edge = v64[4]; const float* beta_edge = v64[5];

  // fork node-side chain (node_mlp -> head_h) onto stream s2
  cudaEventRecord(g_sh.e0, 0);
  cudaStreamWaitEvent(g_sh.s2, g_sh.e0, 0);
  k_node_mlp<<<(NNODES + 255)/256, 256, 0, g_sh.s2>>>(X, w_node, b_node, g_node, beta_node);
  k_head_h<<<NNODES/NPB, 256, 0, g_sh.s2>>>(gatW, gata);
  cudaEventRecord(g_sh.e1, g_sh.s2);

  // edge-side chain on default stream: CSR build + edge MLP
  k_init<<<(NNODES + 255)/256, 256>>>(ei);
  k_convert<<<(NEDGES + 255)/256, 256>>>(ei);
  k_scan1<<<SCANB, 1024>>>();
  k_scan2<<<1, 32>>>();
  k_scan3<<<SCANB, 1024>>>();
  k_edge_mlp<<<(NEDGES + 127)/128, 128>>>(EA, w_edge, b_edge, g_edge, beta_edge, gata, outa);

  // join: k_ev needs head_h's alphas + edge_mlp's projections
  cudaStreamWaitEvent(0, g_sh.e1, 0);

  // layer 1: score-exp precompute, then lean fused aggregation
  k_ev<<<(NNODES*32 + 255)/256, 256>>>();
  k_fagg1<<<(2*NNODES*32 + 255)/256, 256>>>();

  // layer 2
  k_out_h<<<NNODES/NPB, 256>>>(outW, outa);
  k_fagg2ls<<<(NNODES*32 + 255)/256, 256>>>((float*)d_out);
}